// round 13
// baseline (speedup 1.0000x reference)
#include <cuda_runtime.h>
#include <math.h>
#include <stdint.h>

#define Bb 32
#define Nn 64
#define Dd 256
#define PEN 10000.0f
#define INV_TEMP 20.0f

typedef unsigned long long u64;

__device__ float g_A [Bb*Nn*Dd];
__device__ float g_Bm[Bb*Nn*Dd];
__device__ float g_la[Bb*Nn*Nn];
__device__ uint2 g_W1Bh[32*16*32];   // W1c bf16-hi fragments [ct][ks][lane]
__device__ uint2 g_W1Bm[32*16*32];   // W1c bf16-mid fragments
__device__ uint2 g_W2Bh[8*16*32];
__device__ uint2 g_W2Bm[8*16*32];

__device__ __forceinline__ float clip50(float x){ return fminf(fmaxf(x, -50.f), 50.f); }
__device__ __forceinline__ uint32_t pkbf(float lo, float hi){
    uint32_t r; asm("cvt.rn.bf16x2.f32 %0, %1, %2;" : "=r"(r) : "f"(hi), "f"(lo)); return r;
}
__device__ __forceinline__ void split_pair(float x0, float x1, uint32_t &h, uint32_t &m){
    h = pkbf(x0, x1);
    float h0 = __uint_as_float(h << 16);
    float h1 = __uint_as_float(h & 0xFFFF0000u);
    m = pkbf(x0 - h0, x1 - h1);
}
__device__ __forceinline__ void mma_bf16(float* d, const uint32_t* a, uint32_t b0, uint32_t b1){
    asm volatile("mma.sync.aligned.m16n8k16.row.col.f32.bf16.bf16.f32 "
        "{%0,%1,%2,%3}, {%4,%5,%6,%7}, {%8,%9}, {%0,%1,%2,%3};"
        : "+f"(d[0]), "+f"(d[1]), "+f"(d[2]), "+f"(d[3])
        : "r"(a[0]), "r"(a[1]), "r"(a[2]), "r"(a[3]), "r"(b0), "r"(b1));
}
__device__ __forceinline__ u64 pack2(float x, float y){
    u64 r; asm("mov.b64 %0, {%1, %2};" : "=l"(r) : "f"(x), "f"(y)); return r;
}
__device__ __forceinline__ void unpack2(u64 v, float &lo, float &hi){
    asm("mov.b64 {%0, %1}, %2;" : "=f"(lo), "=f"(hi) : "l"(v));
}
__device__ __forceinline__ void fma2(u64 &acc, u64 a, u64 b){
    asm("fma.rn.f32x2 %0, %1, %2, %0;" : "+l"(acc) : "l"(a), "l"(b));
}
__device__ __forceinline__ void cp_async16(uint32_t dst, const void* src){
    asm volatile("cp.async.ca.shared.global [%0], [%1], 16;" :: "r"(dst), "l"(src));
}
#define CP_COMMIT() asm volatile("cp.async.commit_group;")
#define CP_WAIT1()  asm volatile("cp.async.wait_group 1;")
#define CP_WAIT0()  asm volatile("cp.async.wait_group 0;")

// ============ Kernel 0: pack weights into bf16 hi/mid m16n8k16 B-fragments ============
__global__ void __launch_bounds__(256) pack_weights(const float* __restrict__ W1,
                                                    const float* __restrict__ W2)
{
    int gid = blockIdx.x*256 + threadIdx.x;
    int lane = gid & 31;
    if (gid < 16384){
        int ks = (gid >> 5) & 15;
        int ct = gid >> 9;
        int k0 = ks*16 + (lane & 3)*2, n = ct*8 + (lane >> 2);
        const float* W1c = W1 + 512*Dd;
        float v00 = W1c[ k0   *Dd + n], v01 = W1c[(k0+1)*Dd + n];
        float v10 = W1c[(k0+8)*Dd + n], v11 = W1c[(k0+9)*Dd + n];
        uint32_t b0h, b0m, b1h, b1m;
        split_pair(v00, v01, b0h, b0m);
        split_pair(v10, v11, b1h, b1m);
        g_W1Bh[gid] = make_uint2(b0h, b1h);
        g_W1Bm[gid] = make_uint2(b0m, b1m);
    } else if (gid < 20480){
        int idx = gid - 16384;
        int ks = (idx >> 5) & 15;
        int ct = idx >> 9;
        int k0 = ks*16 + (lane & 3)*2, n = ct*8 + (lane >> 2);
        float v00 = W2[ k0   *64 + n], v01 = W2[(k0+1)*64 + n];
        float v10 = W2[(k0+8)*64 + n], v11 = W2[(k0+9)*64 + n];
        uint32_t b0h, b0m, b1h, b1m;
        split_pair(v00, v01, b0h, b0m);
        split_pair(v10, v11, b1h, b1m);
        g_W2Bh[idx] = make_uint2(b0h, b1h);
        g_W2Bm[idx] = make_uint2(b0m, b1m);
    }
}

// ============ Kernel 1: g_A = clip(s_t)@W1a ; g_Bm = clip(s_t1)@W1b + b1 ============
#define P_S0D 0
#define P_S1D 8704
#define P_WT  17408
#define P_SMEM_BYTES ((17408 + 32768)*4)

__global__ void __launch_bounds__(512, 1) precompute_kernel(
    const float* __restrict__ slots_t, const float* __restrict__ slots_t1,
    const float* __restrict__ W1, const float* __restrict__ b1)
{
    extern __shared__ float psm[];
    u64* S0D = reinterpret_cast<u64*>(psm + P_S0D);
    u64* S1D = reinterpret_cast<u64*>(psm + P_S1D);
    float* WT = psm + P_WT;
    const u64* WTu = reinterpret_cast<const u64*>(WT);
    const int ig = blockIdx.x, b = blockIdx.y;
    const int tid = threadIdx.x;
    const int rowbase = b*Nn + ig*16;
    const int gbase = rowbase * Dd;
    const uint32_t wt_smem = (uint32_t)__cvta_generic_to_shared(WT);

    #pragma unroll
    for (int t = 0; t < 2; t++){
        #pragma unroll
        for (int u = 0; u < 4; u++){
            int off = u*8192 + tid*16;
            cp_async16(wt_smem + t*65536 + off,         (const char*)(W1 + t*32*Dd) + off);
            cp_async16(wt_smem + t*65536 + 32768 + off, (const char*)(W1 + (256 + t*32)*Dd) + off);
        }
        CP_COMMIT();
    }
    #pragma unroll
    for (int n = 0; n < 8; n++){
        int idx = tid + n*512;
        int r = idx >> 8, k = idx & 255;
        float v0 = clip50(slots_t [gbase + idx]);
        float v1 = clip50(slots_t1[gbase + idx]);
        S0D[k*17 + r] = pack2(v0, v0);
        S1D[k*17 + r] = pack2(v1, v1);
    }
    __syncthreads();

    const int cp = tid & 127;
    const int rb = (tid >> 7) * 4;
    u64 accA[4], accB[4];
    #pragma unroll
    for (int p=0;p<4;p++){ accA[p]=0ULL; accB[p]=0ULL; }

    for (int t = 0; t < 8; t++){
        if (t < 7) { CP_WAIT1(); } else { CP_WAIT0(); }
        __syncthreads();
        const u64* WS = WTu + (t&1)*8192;
        #pragma unroll 8
        for (int kk = 0; kk < 32; kk++){
            const int k = t*32 + kk;
            u64 wA = WS[kk*128 + cp];
            u64 wB = WS[4096 + kk*128 + cp];
            #pragma unroll
            for (int p=0;p<4;p++){
                fma2(accA[p], S0D[k*17 + rb + p], wA);
                fma2(accB[p], S1D[k*17 + rb + p], wB);
            }
        }
        __syncthreads();
        if (t + 2 < 8){
            const int tn = t + 2;
            #pragma unroll
            for (int u = 0; u < 4; u++){
                int off = u*8192 + tid*16;
                cp_async16(wt_smem + (tn&1)*65536 + off,         (const char*)(W1 + tn*32*Dd) + off);
                cp_async16(wt_smem + (tn&1)*65536 + 32768 + off, (const char*)(W1 + (256 + tn*32)*Dd) + off);
            }
            CP_COMMIT();
        }
    }
    const float2 b1p = *reinterpret_cast<const float2*>(&b1[2*cp]);
    #pragma unroll
    for (int p=0;p<4;p++){
        float lo, hi;
        unpack2(accA[p], lo, hi);
        *reinterpret_cast<float2*>(&g_A[(rowbase + rb + p)*Dd + 2*cp]) = make_float2(lo, hi);
        unpack2(accB[p], lo, hi);
        *reinterpret_cast<float2*>(&g_Bm[(rowbase + rb + p)*Dd + 2*cp]) = make_float2(lo + b1p.x, hi + b1p.y);
    }
}

// ============ Kernel 2: bf16 tensor score kernel, CTA = (i-pair, b), M=128 ============
// Warp tiling: GEMM1 warp = 64 rows x 32 cols (B-LDG 4x less); GEMM2 warp = 64 rows x 8 cols.
#define ZOFF_S1  0                 // [64][260]; overlaid by H2 [128][68] after GEMM1
#define ZOFF_H   16640             // [128][260]
#define ZOFF_STI 49920             // [2][256]
#define ZOFF_AB  50432             // [2][256]
#define ZOFF_B2  50944             // [64]
#define ZOFF_W3  51008             // [64]
#define Z_SMEM_BYTES (51072*4)     // 204288

__global__ void __launch_bounds__(512, 1) score_kernel(
    const float* __restrict__ slots_t, const float* __restrict__ slots_t1,
    const float* __restrict__ alive_t, const float* __restrict__ alive_t1,
    const float* __restrict__ b2, const float* __restrict__ W3,
    const float* __restrict__ b3)
{
    extern __shared__ float sm[];
    float* S1  = sm + ZOFF_S1;    // stride 260
    float* H   = sm + ZOFF_H;     // stride 260
    float* H2  = sm + ZOFF_S1;    // overlays S1 after GEMM1; stride 68
    float* STI = sm + ZOFF_STI;
    float* AB  = sm + ZOFF_AB;
    float* B2S = sm + ZOFF_B2;
    float* W3S = sm + ZOFF_W3;

    const int i0 = blockIdx.x*2, b = blockIdx.y;
    const int tid = threadIdx.x;
    const int lane = tid & 31, w = tid >> 5;
    const int colg = w & 7;           // GEMM1: 32-col group; GEMM2: 8-col group (nt)
    const int rh   = w >> 3;          // row half (64 rows) == i-index i2
    const int tg = lane & 3, gi = lane >> 2;

    // ---- fills ----
    {
        int ii = tid >> 8, k = tid & 255;
        STI[tid] = clip50(slots_t[(b*Nn + i0 + ii)*Dd + k]);
        AB[tid]  = g_A[(b*Nn + i0 + ii)*Dd + k];
    }
    if (tid < 64){ B2S[tid] = b2[tid]; }
    else if (tid < 128){ W3S[tid-64] = W3[tid-64]; }
    for (int idx = tid; idx < Nn*Dd; idx += 512){
        int j = idx >> 8, k = idx & 255;
        S1[j*260 + k] = clip50(slots_t1[(b*Nn + j)*Dd + k]);
    }
    __syncthreads();

    // ---- GEMM1: D1[128r][256c] = |diff| @ W1c  (3xBF16, m16n8k16) ----
    // warp covers rows rh*64 + [0,64) (j = mt2*16+gi (+8), i = i0+rh), cols colg*32 + [0,32)
    float acc[4][4][4];   // [mt2][q][frag]
    #pragma unroll
    for (int m=0;m<4;m++)
        #pragma unroll
        for (int q=0;q<4;q++){ acc[m][q][0]=0.f; acc[m][q][1]=0.f; acc[m][q][2]=0.f; acc[m][q][3]=0.f; }

    for (int ks = 0; ks < 16; ks++){
        const int kA = ks*16 + tg*2, kB = kA + 8;
        float2 tA = *reinterpret_cast<const float2*>(&STI[rh*256 + kA]);
        float2 tB = *reinterpret_cast<const float2*>(&STI[rh*256 + kB]);
        uint32_t ah[4][4], am[4][4];
        #pragma unroll
        for (int m=0;m<4;m++){
            const int j0 = m*16 + gi;
            float2 sA0 = *reinterpret_cast<const float2*>(&S1[ j0   *260 + kA]);
            float2 sA1 = *reinterpret_cast<const float2*>(&S1[(j0+8)*260 + kA]);
            float2 sB0 = *reinterpret_cast<const float2*>(&S1[ j0   *260 + kB]);
            float2 sB1 = *reinterpret_cast<const float2*>(&S1[(j0+8)*260 + kB]);
            split_pair(fabsf(tA.x - sA0.x), fabsf(tA.y - sA0.y), ah[m][0], am[m][0]);
            split_pair(fabsf(tA.x - sA1.x), fabsf(tA.y - sA1.y), ah[m][1], am[m][1]);
            split_pair(fabsf(tB.x - sB0.x), fabsf(tB.y - sB0.y), ah[m][2], am[m][2]);
            split_pair(fabsf(tB.x - sB1.x), fabsf(tB.y - sB1.y), ah[m][3], am[m][3]);
        }
        #pragma unroll
        for (int q=0;q<4;q++){
            const int ct = colg*4 + q;
            uint2 bh = g_W1Bh[ct*512 + ks*32 + lane];
            uint2 bm = g_W1Bm[ct*512 + ks*32 + lane];
            #pragma unroll
            for (int m=0;m<4;m++){
                mma_bf16(acc[m][q], ah[m], bh.x, bh.y);
                mma_bf16(acc[m][q], ah[m], bm.x, bm.y);
                mma_bf16(acc[m][q], am[m], bh.x, bh.y);
            }
        }
    }

    // epilogue: H = relu(D1 + AB[rh][c] + Bm[j][c])
    #pragma unroll
    for (int m=0;m<4;m++){
        const int j0 = m*16 + gi;
        const int r0 = rh*64 + j0;
        #pragma unroll
        for (int q=0;q<4;q++){
            const int c0 = (colg*4 + q)*8 + 2*tg;
            float2 ab = *reinterpret_cast<const float2*>(&AB[rh*256 + c0]);
            float2 bm0 = *reinterpret_cast<const float2*>(&g_Bm[(b*Nn + j0    )*Dd + c0]);
            float2 bm1 = *reinterpret_cast<const float2*>(&g_Bm[(b*Nn + j0 + 8)*Dd + c0]);
            *reinterpret_cast<float2*>(&H[ r0   *260 + c0]) =
                make_float2(fmaxf(acc[m][q][0] + ab.x + bm0.x, 0.f), fmaxf(acc[m][q][1] + ab.y + bm0.y, 0.f));
            *reinterpret_cast<float2*>(&H[(r0+8)*260 + c0]) =
                make_float2(fmaxf(acc[m][q][2] + ab.x + bm1.x, 0.f), fmaxf(acc[m][q][3] + ab.y + bm1.y, 0.f));
        }
    }
    __syncthreads();   // H ready; S1 dead from here

    // ---- GEMM2: D2[128r][64m] = H @ W2  (3xBF16); warp = 64 rows x 8 cols (nt=colg) ----
    float acc2[4][4];
    #pragma unroll
    for (int m=0;m<4;m++){ acc2[m][0]=0.f; acc2[m][1]=0.f; acc2[m][2]=0.f; acc2[m][3]=0.f; }

    for (int ks = 0; ks < 16; ks++){
        const int kA = ks*16 + tg*2, kB = kA + 8;
        uint32_t ah[4][4], am[4][4];
        #pragma unroll
        for (int m=0;m<4;m++){
            const int r0 = rh*64 + m*16 + gi;
            float2 hA0 = *reinterpret_cast<const float2*>(&H[ r0   *260 + kA]);
            float2 hA1 = *reinterpret_cast<const float2*>(&H[(r0+8)*260 + kA]);
            float2 hB0 = *reinterpret_cast<const float2*>(&H[ r0   *260 + kB]);
            float2 hB1 = *reinterpret_cast<const float2*>(&H[(r0+8)*260 + kB]);
            split_pair(hA0.x, hA0.y, ah[m][0], am[m][0]);
            split_pair(hA1.x, hA1.y, ah[m][1], am[m][1]);
            split_pair(hB0.x, hB0.y, ah[m][2], am[m][2]);
            split_pair(hB1.x, hB1.y, ah[m][3], am[m][3]);
        }
        uint2 bh = g_W2Bh[colg*512 + ks*32 + lane];
        uint2 bm = g_W2Bm[colg*512 + ks*32 + lane];
        #pragma unroll
        for (int m=0;m<4;m++){
            mma_bf16(acc2[m], ah[m], bh.x, bh.y);
            mma_bf16(acc2[m], ah[m], bm.x, bm.y);
            mma_bf16(acc2[m], am[m], bh.x, bh.y);
        }
    }
    __syncthreads();   // all old-S1-region reads done before H2 overwrite

    #pragma unroll
    for (int m=0;m<4;m++){
        const int r0 = rh*64 + m*16 + gi;
        const int m0 = colg*8 + 2*tg;
        float2 bb = *reinterpret_cast<const float2*>(&B2S[m0]);
        *reinterpret_cast<float2*>(&H2[ r0   *68 + m0]) =
            make_float2(fmaxf(acc2[m][0] + bb.x, 0.f), fmaxf(acc2[m][1] + bb.y, 0.f));
        *reinterpret_cast<float2*>(&H2[(r0+8)*68 + m0]) =
            make_float2(fmaxf(acc2[m][2] + bb.x, 0.f), fmaxf(acc2[m][3] + bb.y, 0.f));
    }
    __syncthreads();

    // ---- GEMM3 + penalties ----
    if (tid < 128){
        const int row = tid, i2 = row >> 6, j = row & 63;
        float s0=0.f, s1=0.f, s2=0.f, s3=0.f;
        #pragma unroll
        for (int c = 0; c < 64; c += 4){
            s0 = fmaf(H2[row*68 + c  ], W3S[c  ], s0);
            s1 = fmaf(H2[row*68 + c+1], W3S[c+1], s1);
            s2 = fmaf(H2[row*68 + c+2], W3S[c+2], s2);
            s3 = fmaf(H2[row*68 + c+3], W3S[c+3], s3);
        }
        float score = (s0+s1)+(s2+s3) + b3[0];
        if (alive_t [b*Nn + i0 + i2] < 0.5f) score -= PEN;
        if (alive_t1[b*Nn + j] < 0.5f) score -= PEN;
        float la = fminf(fmaxf(score, -PEN), PEN) * INV_TEMP;
        g_la[(b*Nn + i0 + i2)*Nn + j] = la;
    }
}

// ============ Kernel 3: Sinkhorn (1024 threads, fast-math) ============
__global__ void __launch_bounds__(1024) sinkhorn_kernel(
    const float* __restrict__ alive_t, const float* __restrict__ alive_t1,
    float* __restrict__ out)
{
    __shared__ float la[64][65];
    const int b = blockIdx.x;
    const int tid = threadIdx.x;
    const int lane = tid & 31, w = tid >> 5;

    for (int idx = tid; idx < 64*64; idx += 1024)
        la[idx >> 6][idx & 63] = g_la[b*4096 + idx];
    __syncthreads();

    for (int it = 0; it < 20; it++){
        #pragma unroll
        for (int rr = 0; rr < 2; rr++){
            const int i = w*2 + rr;
            float v0 = la[i][lane], v1 = la[i][lane+32];
            float m = fmaxf(v0, v1);
            #pragma unroll
            for (int off = 16; off > 0; off >>= 1) m = fmaxf(m, __shfl_xor_sync(0xffffffffu, m, off));
            float s = __expf(v0 - m) + __expf(v1 - m);
            #pragma unroll
            for (int off = 16; off > 0; off >>= 1) s += __shfl_xor_sync(0xffffffffu, s, off);
            float lse = m + __logf(s);
            la[i][lane] = v0 - lse; la[i][lane+32] = v1 - lse;
        }
        __syncthreads();
        #pragma unroll
        for (int rr = 0; rr < 2; rr++){
            const int j = w*2 + rr;
            float v0 = la[lane][j], v1 = la[lane+32][j];
            float m = fmaxf(v0, v1);
            #pragma unroll
            for (int off = 16; off > 0; off >>= 1) m = fmaxf(m, __shfl_xor_sync(0xffffffffu, m, off));
            float s = __expf(v0 - m) + __expf(v1 - m);
            #pragma unroll
            for (int off = 16; off > 0; off >>= 1) s += __shfl_xor_sync(0xffffffffu, s, off);
            float lse = m + __logf(s);
            la[lane][j] = v0 - lse; la[lane+32][j] = v1 - lse;
        }
        __syncthreads();
    }
    #pragma unroll
    for (int rr = 0; rr < 2; rr++){
        const int i = w*2 + rr;
        float v0 = la[i][lane], v1 = la[i][lane+32];
        float bv; int bi;
        if (v1 > v0){ bv = v1; bi = lane + 32; } else { bv = v0; bi = lane; }
        #pragma unroll
        for (int off = 16; off > 0; off >>= 1){
            float ov = __shfl_xor_sync(0xffffffffu, bv, off);
            int   oi = __shfl_xor_sync(0xffffffffu, bi, off);
            if (ov > bv || (ov == bv && oi < bi)){ bv = ov; bi = oi; }
        }
        if (lane == 0){
            float conf = __expf(bv);
            float matched = (alive_t[b*Nn + i] > 0.5f && alive_t1[b*Nn + bi] > 0.5f && conf > 0.3f) ? 1.f : 0.f;
            out[b*Nn + i]         = (float)bi;
            out[Bb*Nn + b*Nn + i] = matched;
        }
    }
}

// ============ launch ============
extern "C" void kernel_launch(void* const* d_in, const int* in_sizes, int n_in,
                              void* d_out, int out_size)
{
    const float* slots_t  = (const float*)d_in[0];
    const float* slots_t1 = (const float*)d_in[1];
    const float* alive_t  = (const float*)d_in[2];
    const float* alive_t1 = (const float*)d_in[3];
    const float* W1 = (const float*)d_in[4];
    const float* b1 = (const float*)d_in[5];
    const float* W2 = (const float*)d_in[6];
    const float* b2 = (const float*)d_in[7];
    const float* W3 = (const float*)d_in[8];
    const float* b3 = (const float*)d_in[9];
    float* out = (float*)d_out;

    cudaFuncSetAttribute(precompute_kernel, cudaFuncAttributeMaxDynamicSharedMemorySize, P_SMEM_BYTES);
    cudaFuncSetAttribute(score_kernel,      cudaFuncAttributeMaxDynamicSharedMemorySize, Z_SMEM_BYTES);

    pack_weights<<<80, 256>>>(W1, W2);
    precompute_kernel<<<dim3(4, Bb), 512, P_SMEM_BYTES>>>(slots_t, slots_t1, W1, b1);
    score_kernel<<<dim3(Nn/2, Bb), 512, Z_SMEM_BYTES>>>(slots_t, slots_t1, alive_t, alive_t1,
                                                        b2, W3, b3);
    sinkhorn_kernel<<<Bb, 1024>>>(alive_t, alive_t1, out);
}

// round 17
// speedup vs baseline: 1.1696x; 1.1696x over previous
#include <cuda_runtime.h>
#include <math.h>
#include <stdint.h>

#define Bb 32
#define Nn 64
#define Dd 256
#define PEN 10000.0f
#define INV_TEMP 20.0f

typedef unsigned long long u64;

__device__ float g_A [Bb*Nn*Dd];
__device__ float g_Bm[Bb*Nn*Dd];
__device__ float g_la[Bb*Nn*Nn];
__device__ uint2 g_W1Bh[32*16*32];   // W1c bf16-hi fragments [ct][ks][lane]
__device__ uint2 g_W1Bm[32*16*32];   // W1c bf16-mid
__device__ uint2 g_W2Bh[8*16*32];
__device__ uint2 g_W2Bm[8*16*32];
__device__ uint2 g_WAh [32*16*32];   // W1a fragments
__device__ uint2 g_WAm [32*16*32];
__device__ uint2 g_WBh [32*16*32];   // W1b fragments
__device__ uint2 g_WBm [32*16*32];

__device__ __forceinline__ float clip50(float x){ return fminf(fmaxf(x, -50.f), 50.f); }
__device__ __forceinline__ uint32_t pkbf(float lo, float hi){
    uint32_t r; asm("cvt.rn.bf16x2.f32 %0, %1, %2;" : "=r"(r) : "f"(hi), "f"(lo)); return r;
}
__device__ __forceinline__ void split_pair(float x0, float x1, uint32_t &h, uint32_t &m){
    h = pkbf(x0, x1);
    float h0 = __uint_as_float(h << 16);
    float h1 = __uint_as_float(h & 0xFFFF0000u);
    m = pkbf(x0 - h0, x1 - h1);
}
__device__ __forceinline__ void mma_bf16(float* d, const uint32_t* a, uint32_t b0, uint32_t b1){
    asm volatile("mma.sync.aligned.m16n8k16.row.col.f32.bf16.bf16.f32 "
        "{%0,%1,%2,%3}, {%4,%5,%6,%7}, {%8,%9}, {%0,%1,%2,%3};"
        : "+f"(d[0]), "+f"(d[1]), "+f"(d[2]), "+f"(d[3])
        : "r"(a[0]), "r"(a[1]), "r"(a[2]), "r"(a[3]), "r"(b0), "r"(b1));
}

// ============ Kernel 0: pack W1c, W2, W1a, W1b into bf16 hi/mid B-fragments ============
__global__ void __launch_bounds__(256) pack_weights(const float* __restrict__ W1,
                                                    const float* __restrict__ W2)
{
    int gid = blockIdx.x*256 + threadIdx.x;
    int lane = gid & 31;
    if (gid < 16384){
        int ks = (gid >> 5) & 15;
        int ct = gid >> 9;
        int k0 = ks*16 + (lane & 3)*2, n = ct*8 + (lane >> 2);
        const float* W1c = W1 + 512*Dd;
        uint32_t b0h, b0m, b1h, b1m;
        split_pair(W1c[ k0   *Dd + n], W1c[(k0+1)*Dd + n], b0h, b0m);
        split_pair(W1c[(k0+8)*Dd + n], W1c[(k0+9)*Dd + n], b1h, b1m);
        g_W1Bh[gid] = make_uint2(b0h, b1h);
        g_W1Bm[gid] = make_uint2(b0m, b1m);
    } else if (gid < 20480){
        int idx = gid - 16384;
        int ks = (idx >> 5) & 15;
        int ct = idx >> 9;
        int k0 = ks*16 + (lane & 3)*2, n = ct*8 + (lane >> 2);
        uint32_t b0h, b0m, b1h, b1m;
        split_pair(W2[ k0   *64 + n], W2[(k0+1)*64 + n], b0h, b0m);
        split_pair(W2[(k0+8)*64 + n], W2[(k0+9)*64 + n], b1h, b1m);
        g_W2Bh[idx] = make_uint2(b0h, b1h);
        g_W2Bm[idx] = make_uint2(b0m, b1m);
    } else if (gid < 36864){
        int idx = gid - 20480;
        int ks = (idx >> 5) & 15;
        int ct = idx >> 9;
        int k0 = ks*16 + (lane & 3)*2, n = ct*8 + (lane >> 2);
        uint32_t b0h, b0m, b1h, b1m;
        split_pair(W1[ k0   *Dd + n], W1[(k0+1)*Dd + n], b0h, b0m);
        split_pair(W1[(k0+8)*Dd + n], W1[(k0+9)*Dd + n], b1h, b1m);
        g_WAh[idx] = make_uint2(b0h, b1h);
        g_WAm[idx] = make_uint2(b0m, b1m);
    } else if (gid < 53248){
        int idx = gid - 36864;
        int ks = (idx >> 5) & 15;
        int ct = idx >> 9;
        int k0 = ks*16 + (lane & 3)*2, n = ct*8 + (lane >> 2);
        uint32_t b0h, b0m, b1h, b1m;
        split_pair(W1[(256 + k0  )*Dd + n], W1[(256 + k0+1)*Dd + n], b0h, b0m);
        split_pair(W1[(256 + k0+8)*Dd + n], W1[(256 + k0+9)*Dd + n], b1h, b1m);
        g_WBh[idx] = make_uint2(b0h, b1h);
        g_WBm[idx] = make_uint2(b0m, b1m);
    }
}

// ============ Kernel 1: tensor precompute ============
// grid (128, 2): gy=0 -> g_A = clip(s_t)@W1a ; gy=1 -> g_Bm = clip(s_t1)@W1b + b1
// CTA: 16 global rows; warp w: cols w*16..w*16+15 (ct = w*2+q, q<2).
__global__ void __launch_bounds__(512, 1) precompute_kernel(
    const float* __restrict__ slots_t, const float* __restrict__ slots_t1,
    const float* __restrict__ b1)
{
    __shared__ float SD[16*260];
    const int rowbase = blockIdx.x * 16;
    const int gy = blockIdx.y;
    const float* src = gy ? slots_t1 : slots_t;
    const int tid = threadIdx.x;
    const int lane = tid & 31, w = tid >> 5;
    const int tg = lane & 3, gi = lane >> 2;

    #pragma unroll
    for (int e = 0; e < 8; e++){
        int idx = tid + e*512;
        int r = idx >> 8, k = idx & 255;
        SD[r*260 + k] = clip50(src[(rowbase + r)*Dd + k]);
    }
    __syncthreads();

    const uint2* Wh = gy ? g_WBh : g_WAh;
    const uint2* Wm = gy ? g_WBm : g_WAm;

    float acc[2][4];
    #pragma unroll
    for (int q=0;q<2;q++){ acc[q][0]=0.f; acc[q][1]=0.f; acc[q][2]=0.f; acc[q][3]=0.f; }

    for (int ks = 0; ks < 16; ks++){
        const int kA = ks*16 + tg*2, kB = kA + 8;
        float2 sA0 = *reinterpret_cast<const float2*>(&SD[ gi   *260 + kA]);
        float2 sA1 = *reinterpret_cast<const float2*>(&SD[(gi+8)*260 + kA]);
        float2 sB0 = *reinterpret_cast<const float2*>(&SD[ gi   *260 + kB]);
        float2 sB1 = *reinterpret_cast<const float2*>(&SD[(gi+8)*260 + kB]);
        uint32_t ah[4], am[4];
        split_pair(sA0.x, sA0.y, ah[0], am[0]);
        split_pair(sA1.x, sA1.y, ah[1], am[1]);
        split_pair(sB0.x, sB0.y, ah[2], am[2]);
        split_pair(sB1.x, sB1.y, ah[3], am[3]);
        #pragma unroll
        for (int q=0;q<2;q++){
            const int ct = w*2 + q;
            uint2 bh = Wh[ct*512 + ks*32 + lane];
            uint2 bm = Wm[ct*512 + ks*32 + lane];
            mma_bf16(acc[q], ah, bh.x, bh.y);
            mma_bf16(acc[q], ah, bm.x, bm.y);
            mma_bf16(acc[q], am, bh.x, bh.y);
        }
    }

    float* dst = gy ? g_Bm : g_A;
    #pragma unroll
    for (int q=0;q<2;q++){
        const int c0 = (w*2 + q)*8 + 2*tg;
        float b0 = 0.f, b1v = 0.f;
        if (gy){
            float2 bp = *reinterpret_cast<const float2*>(&b1[c0]);
            b0 = bp.x; b1v = bp.y;
        }
        *reinterpret_cast<float2*>(&dst[(rowbase + gi    )*Dd + c0]) =
            make_float2(acc[q][0] + b0, acc[q][1] + b1v);
        *reinterpret_cast<float2*>(&dst[(rowbase + gi + 8)*Dd + c0]) =
            make_float2(acc[q][2] + b0, acc[q][3] + b1v);
    }
}

// ============ Kernel 2: bf16 tensor score kernel, CTA = (i-pair, b), M=128 ============
#define ZOFF_S1  0                 // [64][260]; overlaid by H2 [128][68] after GEMM1
#define ZOFF_H   16640             // [128][260]
#define ZOFF_STI 49920             // [2][256]
#define ZOFF_AB  50432             // [2][256]
#define ZOFF_B2  50944             // [64]
#define ZOFF_W3  51008             // [64]
#define Z_SMEM_BYTES (51072*4)     // 204288

__global__ void __launch_bounds__(512, 1) score_kernel(
    const float* __restrict__ slots_t, const float* __restrict__ slots_t1,
    const float* __restrict__ alive_t, const float* __restrict__ alive_t1,
    const float* __restrict__ b2, const float* __restrict__ W3,
    const float* __restrict__ b3)
{
    extern __shared__ float sm[];
    float* S1  = sm + ZOFF_S1;    // stride 260
    float* H   = sm + ZOFF_H;     // stride 260
    float* H2  = sm + ZOFF_S1;    // overlays S1 after GEMM1; stride 68
    float* STI = sm + ZOFF_STI;
    float* AB  = sm + ZOFF_AB;
    float* B2S = sm + ZOFF_B2;
    float* W3S = sm + ZOFF_W3;

    const int i0 = blockIdx.x*2, b = blockIdx.y;
    const int tid = threadIdx.x;
    const int lane = tid & 31, w = tid >> 5;
    const int mt = w & 7;             // rows mt*16 .. +15 (of 128)
    const int cgrp = w >> 3;          // GEMM1: cols cgrp*128..+127
    const int tg = lane & 3, gi = lane >> 2;

    // ---- fills ----
    {
        int ii = tid >> 8, k = tid & 255;
        STI[tid] = clip50(slots_t[(b*Nn + i0 + ii)*Dd + k]);
        AB[tid]  = g_A[(b*Nn + i0 + ii)*Dd + k];
    }
    if (tid < 64){ B2S[tid] = b2[tid]; }
    else if (tid < 128){ W3S[tid-64] = W3[tid-64]; }
    for (int idx = tid; idx < Nn*Dd; idx += 512){
        int j = idx >> 8, k = idx & 255;
        S1[j*260 + k] = clip50(slots_t1[(b*Nn + j)*Dd + k]);
    }
    __syncthreads();

    const int r0 = mt*16 + gi;        // rows r0, r0+8
    const int ii = mt >> 2;
    const int jj = r0 & 63;

    // ---- GEMM1: D1[128r][256c] = |diff| @ W1c  (3xBF16, m16n8k16) ----
    float acc[16][4];
    #pragma unroll
    for (int q=0;q<16;q++){ acc[q][0]=0.f; acc[q][1]=0.f; acc[q][2]=0.f; acc[q][3]=0.f; }

    for (int ks = 0; ks < 16; ks++){
        const int kA = ks*16 + tg*2, kB = kA + 8;
        float2 tA = *reinterpret_cast<const float2*>(&STI[ii*256 + kA]);
        float2 tB = *reinterpret_cast<const float2*>(&STI[ii*256 + kB]);
        float2 sA0 = *reinterpret_cast<const float2*>(&S1[ jj   *260 + kA]);
        float2 sA1 = *reinterpret_cast<const float2*>(&S1[(jj+8)*260 + kA]);
        float2 sB0 = *reinterpret_cast<const float2*>(&S1[ jj   *260 + kB]);
        float2 sB1 = *reinterpret_cast<const float2*>(&S1[(jj+8)*260 + kB]);
        uint32_t ah[4], am[4];
        split_pair(fabsf(tA.x - sA0.x), fabsf(tA.y - sA0.y), ah[0], am[0]);
        split_pair(fabsf(tA.x - sA1.x), fabsf(tA.y - sA1.y), ah[1], am[1]);
        split_pair(fabsf(tB.x - sB0.x), fabsf(tB.y - sB0.y), ah[2], am[2]);
        split_pair(fabsf(tB.x - sB1.x), fabsf(tB.y - sB1.y), ah[3], am[3]);
        const uint2* pBh = g_W1Bh + (cgrp*16)*512 + ks*32 + lane;
        const uint2* pBm = g_W1Bm + (cgrp*16)*512 + ks*32 + lane;
        #pragma unroll
        for (int q=0;q<16;q++){
            uint2 bh = pBh[q*512];
            uint2 bm = pBm[q*512];
            mma_bf16(acc[q], ah, bh.x, bh.y);
            mma_bf16(acc[q], ah, bm.x, bm.y);
            mma_bf16(acc[q], am, bh.x, bh.y);
        }
    }

    // epilogue: H = relu(D1 + AB[ii][c] + Bm[jj][c])
    #pragma unroll
    for (int q=0;q<16;q++){
        const int c0 = (cgrp*16 + q)*8 + 2*tg;
        float2 ab = *reinterpret_cast<const float2*>(&AB[ii*256 + c0]);
        float2 bm0 = *reinterpret_cast<const float2*>(&g_Bm[(b*Nn + jj    )*Dd + c0]);
        float2 bm1 = *reinterpret_cast<const float2*>(&g_Bm[(b*Nn + jj + 8)*Dd + c0]);
        *reinterpret_cast<float2*>(&H[ r0   *260 + c0]) =
            make_float2(fmaxf(acc[q][0] + ab.x + bm0.x, 0.f), fmaxf(acc[q][1] + ab.y + bm0.y, 0.f));
        *reinterpret_cast<float2*>(&H[(r0+8)*260 + c0]) =
            make_float2(fmaxf(acc[q][2] + ab.x + bm1.x, 0.f), fmaxf(acc[q][3] + ab.y + bm1.y, 0.f));
    }
    __syncthreads();   // H ready; S1 dead from here

    // ---- GEMM2: D2[128r][64m] = H @ W2  (3xBF16) ----
    float acc2[4][4];
    #pragma unroll
    for (int q=0;q<4;q++){ acc2[q][0]=0.f; acc2[q][1]=0.f; acc2[q][2]=0.f; acc2[q][3]=0.f; }

    for (int ks = 0; ks < 16; ks++){
        const int kA = ks*16 + tg*2, kB = kA + 8;
        float2 hA0 = *reinterpret_cast<const float2*>(&H[ r0   *260 + kA]);
        float2 hA1 = *reinterpret_cast<const float2*>(&H[(r0+8)*260 + kA]);
        float2 hB0 = *reinterpret_cast<const float2*>(&H[ r0   *260 + kB]);
        float2 hB1 = *reinterpret_cast<const float2*>(&H[(r0+8)*260 + kB]);
        uint32_t ah[4], am[4];
        split_pair(hA0.x, hA0.y, ah[0], am[0]);
        split_pair(hA1.x, hA1.y, ah[1], am[1]);
        split_pair(hB0.x, hB0.y, ah[2], am[2]);
        split_pair(hB1.x, hB1.y, ah[3], am[3]);
        #pragma unroll
        for (int q=0;q<4;q++){
            const int nt = cgrp*4 + q;
            uint2 bh = g_W2Bh[nt*512 + ks*32 + lane];
            uint2 bm = g_W2Bm[nt*512 + ks*32 + lane];
            mma_bf16(acc2[q], ah, bh.x, bh.y);
            mma_bf16(acc2[q], ah, bm.x, bm.y);
            mma_bf16(acc2[q], am, bh.x, bh.y);
        }
    }
    __syncthreads();   // all old-S1 reads done before H2 overwrite

    #pragma unroll
    for (int q=0;q<4;q++){
        const int m0 = (cgrp*4 + q)*8 + 2*tg;
        float2 bb = *reinterpret_cast<const float2*>(&B2S[m0]);
        *reinterpret_cast<float2*>(&H2[ r0   *68 + m0]) =
            make_float2(fmaxf(acc2[q][0] + bb.x, 0.f), fmaxf(acc2[q][1] + bb.y, 0.f));
        *reinterpret_cast<float2*>(&H2[(r0+8)*68 + m0]) =
            make_float2(fmaxf(acc2[q][2] + bb.x, 0.f), fmaxf(acc2[q][3] + bb.y, 0.f));
    }
    __syncthreads();

    // ---- GEMM3 + penalties ----
    if (tid < 128){
        const int row = tid, i2 = row >> 6, j = row & 63;
        float s0=0.f, s1=0.f, s2=0.f, s3=0.f;
        #pragma unroll
        for (int c = 0; c < 64; c += 4){
            s0 = fmaf(H2[row*68 + c  ], W3S[c  ], s0);
            s1 = fmaf(H2[row*68 + c+1], W3S[c+1], s1);
            s2 = fmaf(H2[row*68 + c+2], W3S[c+2], s2);
            s3 = fmaf(H2[row*68 + c+3], W3S[c+3], s3);
        }
        float score = (s0+s1)+(s2+s3) + b3[0];
        if (alive_t [b*Nn + i0 + i2] < 0.5f) score -= PEN;
        if (alive_t1[b*Nn + j] < 0.5f) score -= PEN;
        float la = fminf(fmaxf(score, -PEN), PEN) * INV_TEMP;
        g_la[(b*Nn + i0 + i2)*Nn + j] = la;
    }
}

// ============ Kernel 3: Sinkhorn (1024 threads, fast-math) ============
__global__ void __launch_bounds__(1024) sinkhorn_kernel(
    const float* __restrict__ alive_t, const float* __restrict__ alive_t1,
    float* __restrict__ out)
{
    __shared__ float la[64][65];
    const int b = blockIdx.x;
    const int tid = threadIdx.x;
    const int lane = tid & 31, w = tid >> 5;

    for (int idx = tid; idx < 64*64; idx += 1024)
        la[idx >> 6][idx & 63] = g_la[b*4096 + idx];
    __syncthreads();

    for (int it = 0; it < 20; it++){
        #pragma unroll
        for (int rr = 0; rr < 2; rr++){
            const int i = w*2 + rr;
            float v0 = la[i][lane], v1 = la[i][lane+32];
            float m = fmaxf(v0, v1);
            #pragma unroll
            for (int off = 16; off > 0; off >>= 1) m = fmaxf(m, __shfl_xor_sync(0xffffffffu, m, off));
            float s = __expf(v0 - m) + __expf(v1 - m);
            #pragma unroll
            for (int off = 16; off > 0; off >>= 1) s += __shfl_xor_sync(0xffffffffu, s, off);
            float lse = m + __logf(s);
            la[i][lane] = v0 - lse; la[i][lane+32] = v1 - lse;
        }
        __syncthreads();
        #pragma unroll
        for (int rr = 0; rr < 2; rr++){
            const int j = w*2 + rr;
            float v0 = la[lane][j], v1 = la[lane+32][j];
            float m = fmaxf(v0, v1);
            #pragma unroll
            for (int off = 16; off > 0; off >>= 1) m = fmaxf(m, __shfl_xor_sync(0xffffffffu, m, off));
            float s = __expf(v0 - m) + __expf(v1 - m);
            #pragma unroll
            for (int off = 16; off > 0; off >>= 1) s += __shfl_xor_sync(0xffffffffu, s, off);
            float lse = m + __logf(s);
            la[lane][j] = v0 - lse; la[lane+32][j] = v1 - lse;
        }
        __syncthreads();
    }
    #pragma unroll
    for (int rr = 0; rr < 2; rr++){
        const int i = w*2 + rr;
        float v0 = la[i][lane], v1 = la[i][lane+32];
        float bv; int bi;
        if (v1 > v0){ bv = v1; bi = lane + 32; } else { bv = v0; bi = lane; }
        #pragma unroll
        for (int off = 16; off > 0; off >>= 1){
            float ov = __shfl_xor_sync(0xffffffffu, bv, off);
            int   oi = __shfl_xor_sync(0xffffffffu, bi, off);
            if (ov > bv || (ov == bv && oi < bi)){ bv = ov; bi = oi; }
        }
        if (lane == 0){
            float conf = __expf(bv);
            float matched = (alive_t[b*Nn + i] > 0.5f && alive_t1[b*Nn + bi] > 0.5f && conf > 0.3f) ? 1.f : 0.f;
            out[b*Nn + i]         = (float)bi;
            out[Bb*Nn + b*Nn + i] = matched;
        }
    }
}

// ============ launch ============
extern "C" void kernel_launch(void* const* d_in, const int* in_sizes, int n_in,
                              void* d_out, int out_size)
{
    const float* slots_t  = (const float*)d_in[0];
    const float* slots_t1 = (const float*)d_in[1];
    const float* alive_t  = (const float*)d_in[2];
    const float* alive_t1 = (const float*)d_in[3];
    const float* W1 = (const float*)d_in[4];
    const float* b1 = (const float*)d_in[5];
    const float* W2 = (const float*)d_in[6];
    const float* b2 = (const float*)d_in[7];
    const float* W3 = (const float*)d_in[8];
    const float* b3 = (const float*)d_in[9];
    float* out = (float*)d_out;

    cudaFuncSetAttribute(score_kernel, cudaFuncAttributeMaxDynamicSharedMemorySize, Z_SMEM_BYTES);

    pack_weights<<<208, 256>>>(W1, W2);
    precompute_kernel<<<dim3(128, 2), 512>>>(slots_t, slots_t1, b1);
    score_kernel<<<dim3(Nn/2, Bb), 512, Z_SMEM_BYTES>>>(slots_t, slots_t1, alive_t, alive_t1,
                                                        b2, W3, b3);
    sinkhorn_kernel<<<Bb, 1024>>>(alive_t, alive_t1, out);
}